// round 5
// baseline (speedup 1.0000x reference)
#include <cuda_runtime.h>
#include <math.h>

// Fixed shapes: x (4, 32, 8192, 64) fp32, token_positions = arange(8192)
#define SEQ       8192
#define NF4_ROW   16                  // 64 floats / 4 per row
#define BH        128                 // 4*32 slices
#define CHUNK     4                   // bh-slices per thread
#define NCHUNK    (BH / CHUNK)        // 32
#define PTILE     16                  // positions per block
#define SLICE_F4  (SEQ * NF4_ROW)     // 131072 float4 per slice
#define LOG2_THETA 13.287712379549449 // log2(10000)

__global__ void __launch_bounds__(256, 8)
rope_fused(const float4* __restrict__ x, float4* __restrict__ out,
           const int* __restrict__ pos) {
    // Per-block trig table: 16 positions x 32 freqs x {cos,sin} = 4 KB.
    __shared__ float2 s_tab[PTILE][32];
    __shared__ float  s_invf[32];

    int t = threadIdx.x;
    if (t < 32)
        s_invf[t] = (float)exp2(-(double)t * (LOG2_THETA / 32.0));
    __syncthreads();

    int j     = t & (NF4_ROW - 1);               // float4 within row (0..15)
    int pl    = t >> 4;                          // local position (0..15)
    int b     = blockIdx.x;
    int p0    = (b & (SEQ / PTILE - 1)) * PTILE; // position tile base
    int chunk = b >> 9;                          // 0..31 (which 4 bh-slices)

    // Phase 1: fill the block trig table (2 sincosf per thread).
    #pragma unroll
    for (int idx = t; idx < PTILE * 32; idx += 256) {
        int lp = idx >> 5;
        int k  = idx & 31;
        float ang = (float)__ldg(&pos[p0 + lp]) * s_invf[k];
        float s, c;
        sincosf(ang, &s, &c);
        s_tab[lp][k] = make_float2(c, s);
    }
    __syncthreads();

    // Phase 2: pure memory loop — read trig once from smem, rotate 4 slices.
    float4 tr = *(const float4*)&s_tab[pl][2 * j];   // {c0, s0, c1, s1}

    size_t base = (size_t)chunk * CHUNK * SLICE_F4
                + (size_t)(p0 + pl) * NF4_ROW + j;
    const float4* xp = x   + base;
    float4*       op = out + base;

    float4 v0 = __ldcs(&xp[0 * SLICE_F4]);
    float4 v1 = __ldcs(&xp[1 * SLICE_F4]);
    float4 v2 = __ldcs(&xp[2 * SLICE_F4]);
    float4 v3 = __ldcs(&xp[3 * SLICE_F4]);

    float4 o;
    o.x = tr.x * v0.x - tr.y * v0.y;  o.y = tr.y * v0.x + tr.x * v0.y;
    o.z = tr.z * v0.z - tr.w * v0.w;  o.w = tr.w * v0.z + tr.z * v0.w;
    __stcs(&op[0 * SLICE_F4], o);
    o.x = tr.x * v1.x - tr.y * v1.y;  o.y = tr.y * v1.x + tr.x * v1.y;
    o.z = tr.z * v1.z - tr.w * v1.w;  o.w = tr.w * v1.z + tr.z * v1.w;
    __stcs(&op[1 * SLICE_F4], o);
    o.x = tr.x * v2.x - tr.y * v2.y;  o.y = tr.y * v2.x + tr.x * v2.y;
    o.z = tr.z * v2.z - tr.w * v2.w;  o.w = tr.w * v2.z + tr.z * v2.w;
    __stcs(&op[2 * SLICE_F4], o);
    o.x = tr.x * v3.x - tr.y * v3.y;  o.y = tr.y * v3.x + tr.x * v3.y;
    o.z = tr.z * v3.z - tr.w * v3.w;  o.w = tr.w * v3.z + tr.z * v3.w;
    __stcs(&op[3 * SLICE_F4], o);
}

extern "C" void kernel_launch(void* const* d_in, const int* in_sizes, int n_in,
                              void* d_out, int out_size) {
    const float4* x   = (const float4*)d_in[0];
    const int*    pos = (const int*)d_in[1];
    float4*       out = (float4*)d_out;

    // grid: 512 position-tiles * 32 bh-chunks = 16384 blocks of 256
    int nblocks = (SEQ / PTILE) * NCHUNK;
    rope_fused<<<nblocks, 256>>>(x, out, pos);
}

// round 6
// speedup vs baseline: 1.0112x; 1.0112x over previous
#include <cuda_runtime.h>
#include <math.h>

// Fixed shapes: x (4, 32, 8192, 64) fp32, token_positions = arange(8192)
#define SEQ       8192
#define NF4_ROW   16                  // 64 floats / 4 per row
#define BH        128                 // 4*32 slices
#define CHUNK     4                   // bh-slices per thread
#define NCHUNK    (BH / CHUNK)        // 32
#define PTILE     16                  // positions per block
#define SLICE_F4  (SEQ * NF4_ROW)     // 131072 float4 per slice
#define LOG2_THETA 13.2877123795494489f // log2(10000), fp32

__global__ void __launch_bounds__(256, 8)
rope_fused(const float4* __restrict__ x, float4* __restrict__ out,
           const int* __restrict__ pos) {
    __shared__ float2 s_tab[PTILE][32];   // 4 KB block trig table

    int t     = threadIdx.x;
    int j     = t & (NF4_ROW - 1);               // float4 within row (0..15)
    int pl    = t >> 4;                          // local position (0..15)
    int b     = blockIdx.x;
    int p0    = (b & (SEQ / PTILE - 1)) * PTILE; // position tile base
    int chunk = b >> 9;                          // 0..31 (which 4 bh-slices)

    // ---- Issue ALL global loads FIRST: DRAM latency covers the trig phase ----
    size_t base = (size_t)chunk * CHUNK * SLICE_F4
                + (size_t)(p0 + pl) * NF4_ROW + j;
    const float4* xp = x   + base;
    float4*       op = out + base;

    float4 v0 = __ldcs(&xp[0 * SLICE_F4]);
    float4 v1 = __ldcs(&xp[1 * SLICE_F4]);
    float4 v2 = __ldcs(&xp[2 * SLICE_F4]);
    float4 v3 = __ldcs(&xp[3 * SLICE_F4]);

    // ---- Trig phase (overlapped with the loads above) ----
    // invf = 10000^(-k/32) in fp32 via exp2f: <=2 ulp => angle err <~7e-4 rad
    // worst-case at k=1; rms output error ~1e-4, far under the 1e-3 budget.
    {
        int k  = t & 31;                 // frequency
        int lp = t >> 5;                 // local positions lp, lp+8
        float invf = exp2f(-(float)k * (LOG2_THETA / 32.0f));
        float s, c;
        float pa = (float)__ldg(&pos[p0 + lp]) * invf;
        sincosf(pa, &s, &c);
        s_tab[lp][k] = make_float2(c, s);
        float pb = (float)__ldg(&pos[p0 + lp + 8]) * invf;
        sincosf(pb, &s, &c);
        s_tab[lp + 8][k] = make_float2(c, s);
    }
    __syncthreads();

    float4 tr = *(const float4*)&s_tab[pl][2 * j];   // {c0, s0, c1, s1}

    // ---- Rotate + store ----
    float4 o;
    o.x = tr.x * v0.x - tr.y * v0.y;  o.y = tr.y * v0.x + tr.x * v0.y;
    o.z = tr.z * v0.z - tr.w * v0.w;  o.w = tr.w * v0.z + tr.z * v0.w;
    __stcs(&op[0 * SLICE_F4], o);
    o.x = tr.x * v1.x - tr.y * v1.y;  o.y = tr.y * v1.x + tr.x * v1.y;
    o.z = tr.z * v1.z - tr.w * v1.w;  o.w = tr.w * v1.z + tr.z * v1.w;
    __stcs(&op[1 * SLICE_F4], o);
    o.x = tr.x * v2.x - tr.y * v2.y;  o.y = tr.y * v2.x + tr.x * v2.y;
    o.z = tr.z * v2.z - tr.w * v2.w;  o.w = tr.w * v2.z + tr.z * v2.w;
    __stcs(&op[2 * SLICE_F4], o);
    o.x = tr.x * v3.x - tr.y * v3.y;  o.y = tr.y * v3.x + tr.x * v3.y;
    o.z = tr.z * v3.z - tr.w * v3.w;  o.w = tr.w * v3.z + tr.z * v3.w;
    __stcs(&op[3 * SLICE_F4], o);
}

extern "C" void kernel_launch(void* const* d_in, const int* in_sizes, int n_in,
                              void* d_out, int out_size) {
    const float4* x   = (const float4*)d_in[0];
    const int*    pos = (const int*)d_in[1];
    float4*       out = (float4*)d_out;

    // grid: 512 position-tiles * 32 bh-chunks = 16384 blocks of 256
    int nblocks = (SEQ / PTILE) * NCHUNK;
    rope_fused<<<nblocks, 256>>>(x, out, pos);
}

// round 7
// speedup vs baseline: 1.0199x; 1.0086x over previous
#include <cuda_runtime.h>
#include <math.h>

// Fixed shapes: x (4, 32, 8192, 64) fp32, token_positions = arange(8192)
#define SEQ       8192
#define NF4_ROW   16                  // 64 floats / 4 per row
#define BH        128                 // 4*32 slices
#define CHUNK     4                   // bh-slices per thread
#define NCHUNK    (BH / CHUNK)        // 32
#define PTILE     16                  // positions per block
#define SLICE_F4  (SEQ * NF4_ROW)     // 131072 float4 per slice
#define LOG2_THETA 13.2877123795494489f // log2(10000), fp32

// (256, 6): ~42-reg budget so all 4 in-flight float4 loads stay in registers
// across the trig phase + barrier. R4-R6 showed occupancy (61/85/95%) is
// non-binding; R6 showed the 32-reg cap causes spills (L1% 40->53).
__global__ void __launch_bounds__(256, 6)
rope_fused(const float4* __restrict__ x, float4* __restrict__ out,
           const int* __restrict__ pos) {
    __shared__ float2 s_tab[PTILE][32];   // 4 KB block trig table

    int t     = threadIdx.x;
    int j     = t & (NF4_ROW - 1);               // float4 within row (0..15)
    int pl    = t >> 4;                          // local position (0..15)
    int b     = blockIdx.x;
    int p0    = (b & (SEQ / PTILE - 1)) * PTILE; // position tile base
    int chunk = b >> 9;                          // 0..31 (which 4 bh-slices)

    // ---- Issue ALL global loads FIRST: DRAM latency covers the trig phase ----
    size_t base = (size_t)chunk * CHUNK * SLICE_F4
                + (size_t)(p0 + pl) * NF4_ROW + j;
    const float4* xp = x   + base;
    float4*       op = out + base;

    float4 v0 = __ldcs(&xp[0 * SLICE_F4]);
    float4 v1 = __ldcs(&xp[1 * SLICE_F4]);
    float4 v2 = __ldcs(&xp[2 * SLICE_F4]);
    float4 v3 = __ldcs(&xp[3 * SLICE_F4]);

    // ---- Trig phase (runs under the memory latency of the loads above) ----
    // invf = 10000^(-k/32) fp32 exp2f: rel_err 6.3e-5 measured (budget 1e-3).
    {
        int k  = t & 31;                 // frequency
        int lp = t >> 5;                 // local positions lp, lp+8
        float invf = exp2f(-(float)k * (LOG2_THETA / 32.0f));
        float s, c;
        float pa = (float)__ldg(&pos[p0 + lp]) * invf;
        sincosf(pa, &s, &c);
        s_tab[lp][k] = make_float2(c, s);
        float pb = (float)__ldg(&pos[p0 + lp + 8]) * invf;
        sincosf(pb, &s, &c);
        s_tab[lp + 8][k] = make_float2(c, s);
    }
    __syncthreads();

    float4 tr = *(const float4*)&s_tab[pl][2 * j];   // {c0, s0, c1, s1}

    // ---- Rotate + store ----
    float4 o;
    o.x = tr.x * v0.x - tr.y * v0.y;  o.y = tr.y * v0.x + tr.x * v0.y;
    o.z = tr.z * v0.z - tr.w * v0.w;  o.w = tr.w * v0.z + tr.z * v0.w;
    __stcs(&op[0 * SLICE_F4], o);
    o.x = tr.x * v1.x - tr.y * v1.y;  o.y = tr.y * v1.x + tr.x * v1.y;
    o.z = tr.z * v1.z - tr.w * v1.w;  o.w = tr.w * v1.z + tr.z * v1.w;
    __stcs(&op[1 * SLICE_F4], o);
    o.x = tr.x * v2.x - tr.y * v2.y;  o.y = tr.y * v2.x + tr.x * v2.y;
    o.z = tr.z * v2.z - tr.w * v2.w;  o.w = tr.w * v2.z + tr.z * v2.w;
    __stcs(&op[2 * SLICE_F4], o);
    o.x = tr.x * v3.x - tr.y * v3.y;  o.y = tr.y * v3.x + tr.x * v3.y;
    o.z = tr.z * v3.z - tr.w * v3.w;  o.w = tr.w * v3.z + tr.z * v3.w;
    __stcs(&op[3 * SLICE_F4], o);
}

extern "C" void kernel_launch(void* const* d_in, const int* in_sizes, int n_in,
                              void* d_out, int out_size) {
    const float4* x   = (const float4*)d_in[0];
    const int*    pos = (const int*)d_in[1];
    float4*       out = (float4*)d_out;

    // grid: 512 position-tiles * 32 bh-chunks = 16384 blocks of 256
    int nblocks = (SEQ / PTILE) * NCHUNK;
    rope_fused<<<nblocks, 256>>>(x, out, pos);
}